// round 10
// baseline (speedup 1.0000x reference)
#include <cuda_runtime.h>
#include <cuda_fp16.h>
#include <math.h>

// Problem constants (fixed by the dataset)
#define N_NODES 100000
#define E_EDGES 1600000
#define IN_C    128
#define HID_C   128
#define OUT_C   64

#define SCAN_B   512
#define SCAN_NB  ((N_NODES + SCAN_B) / SCAN_B + 1)

typedef unsigned int uint;

// ---------------------------------------------------------------------------
// Scratch: __device__ globals
// ---------------------------------------------------------------------------
__device__ int    g_is64;
__device__ int    g_rowptr[N_NODES + 1];
__device__ int    g_cur   [N_NODES];
__device__ int    g_csrc  [E_EDGES];
__device__ int    g_bsum  [SCAN_NB];
__device__ float  g_dinv  [N_NODES];
__device__ __half g_hh    [(size_t)N_NODES * 128];  // GEMM output (fp16, gather input)
__device__ float  g_a     [(size_t)N_NODES * 128];  // aggregated output (fp32, GEMM input)

// ---------------------------------------------------------------------------
// tf32 helpers
// ---------------------------------------------------------------------------
__device__ __forceinline__ float to_tf32(float x) {
    float y;
    asm("cvt.rna.tf32.f32 %0, %1;" : "=f"(y) : "f"(x));
    return y;
}

__device__ __forceinline__ void mma_tf32(float c[4],
                                         uint a0, uint a1, uint a2, uint a3,
                                         uint b0, uint b1) {
    asm volatile(
        "mma.sync.aligned.m16n8k8.row.col.f32.tf32.tf32.f32 "
        "{%0,%1,%2,%3}, {%4,%5,%6,%7}, {%8,%9}, {%0,%1,%2,%3};"
        : "+f"(c[0]), "+f"(c[1]), "+f"(c[2]), "+f"(c[3])
        : "r"(a0), "r"(a1), "r"(a2), "r"(a3), "r"(b0), "r"(b1));
}

__device__ __forceinline__ int edge_val(const void* __restrict__ ei, long long idx) {
    if (g_is64) return (int)((const long long*)ei)[idx];
    return ((const int*)ei)[idx];
}

// Unpack 8 halves (uint4) into 8 floats
__device__ __forceinline__ void h8_to_f8(uint4 p, float f[8]) {
    float2 a = __half22float2(*reinterpret_cast<__half2*>(&p.x));
    float2 b = __half22float2(*reinterpret_cast<__half2*>(&p.y));
    float2 c = __half22float2(*reinterpret_cast<__half2*>(&p.z));
    float2 d = __half22float2(*reinterpret_cast<__half2*>(&p.w));
    f[0] = a.x; f[1] = a.y; f[2] = b.x; f[3] = b.y;
    f[4] = c.x; f[5] = c.y; f[6] = d.x; f[7] = d.y;
}

// ---------------------------------------------------------------------------
// Setup: zero rowptr + parallel dtype detect (warp ballot, block 0)
// ---------------------------------------------------------------------------
__global__ void setup_kernel(const int* __restrict__ ei32) {
    int i = blockIdx.x * blockDim.x + threadIdx.x;
    if (i <= N_NODES) g_rowptr[i] = 0;
    if (blockIdx.x == 0 && threadIdx.x < 32) {
        int nz = (ei32[2 * threadIdx.x + 1] != 0) ? 1 : 0;
        uint any_nz = __ballot_sync(0xffffffffu, nz);
        if (threadIdx.x == 0) g_is64 = (any_nz == 0u) ? 1 : 0;
    }
}

__global__ void hist_kernel(const void* __restrict__ ei) {
    int e = blockIdx.x * blockDim.x + threadIdx.x;
    if (e < E_EDGES) {
        int d = edge_val(ei, (long long)E_EDGES + e);
        atomicAdd(&g_rowptr[d + 1], 1);
    }
}

// Per-block inclusive scan; also computes dinv from the raw count it loads.
// g_bsum[b] <- block b total (inclusive scan last element).
__global__ void scan_block_kernel() {
    __shared__ int s[SCAN_B];
    const int t   = threadIdx.x;
    const int idx = blockIdx.x * SCAN_B + t;
    int v = (idx <= N_NODES) ? g_rowptr[idx] : 0;
    if (idx >= 1 && idx <= N_NODES) g_dinv[idx - 1] = rsqrtf((float)(v + 1));
    s[t] = v;
    __syncthreads();
    #pragma unroll
    for (int off = 1; off < SCAN_B; off <<= 1) {
        int add = (t >= off) ? s[t - off] : 0;
        __syncthreads();
        s[t] += add;
        __syncthreads();
    }
    if (idx <= N_NODES) g_rowptr[idx] = s[t];
    if (t == SCAN_B - 1) g_bsum[blockIdx.x] = s[t];
}

// Finish: block b adds sum(bsum[0..b-1]) computed by in-block reduction.
__global__ void __launch_bounds__(SCAN_B)
scan_finish_kernel() {
    __shared__ int red[SCAN_B / 32];
    const int t = threadIdx.x;
    const int b = blockIdx.x;
    int val = (t < b) ? g_bsum[t] : 0;    // b <= SCAN_NB-1 < SCAN_B
    #pragma unroll
    for (int o = 16; o; o >>= 1) val += __shfl_xor_sync(0xffffffffu, val, o);
    if ((t & 31) == 0) red[t >> 5] = val;
    __syncthreads();
    if (t == 0) {
        int s = 0;
        #pragma unroll
        for (int i = 0; i < SCAN_B / 32; ++i) s += red[i];
        red[0] = s;
    }
    __syncthreads();
    const int off = red[0];

    const int idx = b * SCAN_B + t;
    if (idx > N_NODES) return;
    int v = g_rowptr[idx] + off;
    g_rowptr[idx] = v;
    if (idx < N_NODES) g_cur[idx] = v;
}

__global__ void fill_csr_kernel(const void* __restrict__ ei) {
    int e = blockIdx.x * blockDim.x + threadIdx.x;
    if (e < E_EDGES) {
        int s = edge_val(ei, e);
        int d = edge_val(ei, (long long)E_EDGES + e);
        int pos = atomicAdd(&g_cur[d], 1);
        g_csrc[pos] = s;
    }
}

// ---------------------------------------------------------------------------
// Tensor-core GEMM (tf32 HMMA):  g_hh[r, :] = (half) f(X[r, :]) @ W
// ---------------------------------------------------------------------------
template<int COLS, bool PRERELU>
__global__ void __launch_bounds__(256)
gemm_tc_kernel(const float* __restrict__ Xin,
               const float* __restrict__ W,
               const float* __restrict__ bprev) {
    constexpr int K    = 128;
    constexpr int KT   = 32;
    constexpr int ROWS = 128;
    constexpr int WN   = COLS / 2;
    constexpr int MT   = 2;
    constexpr int NT   = WN / 8;
    constexpr int XPAD = 4;
    constexpr int WPAD = 4;

    __shared__ float xs[ROWS][KT + XPAD];
    __shared__ float ws[KT][COLS + WPAD];

    const float* X = Xin ? Xin : g_a;
    const int t    = threadIdx.x;
    const int lane = t & 31;
    const int w    = t >> 5;
    const int wm   = w & 3;
    const int wn   = w >> 2;
    const int g    = lane >> 2;
    const int tig  = lane & 3;
    const int row0 = blockIdx.x * ROWS;

    float acc[MT][NT][4];
    #pragma unroll
    for (int m = 0; m < MT; ++m)
        #pragma unroll
        for (int n = 0; n < NT; ++n)
            #pragma unroll
            for (int i = 0; i < 4; ++i) acc[m][n][i] = 0.0f;

    #pragma unroll 1
    for (int kc = 0; kc < K; kc += KT) {
        for (int i = t; i < KT * COLS; i += 256) {
            const int k = i / COLS;
            const int n = i % COLS;
            ws[k][n] = to_tf32(W[(kc + k) * COLS + n]);
        }
        for (int i = t; i < ROWS * KT; i += 256) {
            const int r = i >> 5;
            const int k = i & (KT - 1);
            const int rr = row0 + r;
            float v = 0.0f;
            if (rr < N_NODES) {
                v = X[(size_t)rr * K + kc + k];
                if (PRERELU) v = fmaxf(v + bprev[kc + k], 0.0f);
            }
            xs[r][k] = to_tf32(v);
        }
        __syncthreads();

        #pragma unroll
        for (int ks = 0; ks < KT / 8; ++ks) {
            const int kb = ks * 8;
            uint a[MT][4];
            #pragma unroll
            for (int m = 0; m < MT; ++m) {
                const int ar = wm * 32 + m * 16;
                a[m][0] = __float_as_uint(xs[ar + g    ][kb + tig    ]);
                a[m][1] = __float_as_uint(xs[ar + g + 8][kb + tig    ]);
                a[m][2] = __float_as_uint(xs[ar + g    ][kb + tig + 4]);
                a[m][3] = __float_as_uint(xs[ar + g + 8][kb + tig + 4]);
            }
            #pragma unroll
            for (int n = 0; n < NT; ++n) {
                const int nc = wn * WN + n * 8 + g;
                const uint b0 = __float_as_uint(ws[kb + tig    ][nc]);
                const uint b1 = __float_as_uint(ws[kb + tig + 4][nc]);
                #pragma unroll
                for (int m = 0; m < MT; ++m)
                    mma_tf32(acc[m][n], a[m][0], a[m][1], a[m][2], a[m][3], b0, b1);
            }
        }
        __syncthreads();
    }

    #pragma unroll
    for (int m = 0; m < MT; ++m) {
        const int r0 = row0 + wm * 32 + m * 16 + g;
        #pragma unroll
        for (int n = 0; n < NT; ++n) {
            const int col = wn * WN + n * 8 + 2 * tig;
            if (r0 < N_NODES)
                *reinterpret_cast<__half2*>(&g_hh[(size_t)r0 * COLS + col]) =
                    __floats2half2_rn(acc[m][n][0], acc[m][n][1]);
            if (r0 + 8 < N_NODES)
                *reinterpret_cast<__half2*>(&g_hh[(size_t)(r0 + 8) * COLS + col]) =
                    __floats2half2_rn(acc[m][n][2], acc[m][n][3]);
        }
    }
}

// ---------------------------------------------------------------------------
// CSR gather, 128 cols fp16 -> fp32. Warp per node, SPLIT into 2 half-warps:
// each half processes alternate neighbors, lane loads uint4 (8 halves).
// One warp LDG.128 covers 2 edges. Partials combined via shfl_xor(16).
// ---------------------------------------------------------------------------
__global__ void agg_gather128_kernel() {
    const int v    = blockIdx.x * (blockDim.x >> 5) + (threadIdx.x >> 5);
    const int lane = threadIdx.x & 31;
    if (v >= N_NODES) return;

    const int h  = lane >> 4;        // half id (0/1)
    const int hl = lane & 15;        // lane-in-half: cols [8*hl, 8*hl+8)
    const int   r0 = g_rowptr[v];
    const int   r1 = g_rowptr[v + 1];
    const float dv = g_dinv[v];

    const uint4* H = reinterpret_cast<const uint4*>(g_hh);   // 16 uint4 per row

    float acc[8];
    {
        float f[8];
        h8_to_f8(H[(size_t)v * 16 + hl], f);
        #pragma unroll
        for (int i = 0; i < 8; ++i) acc[i] = (h == 0) ? dv * f[i] : 0.0f;
    }

    int j = r0;
    for (; j + 3 < r1; j += 4) {     // 4 edges in flight (2 per half)
        const int   i0 = j + h;
        const int   i1 = j + 2 + h;
        const int   s0 = g_csrc[i0];
        const int   s1 = g_csrc[i1];
        const float w0 = g_dinv[s0];
        const float w1 = g_dinv[s1];
        float f0[8], f1[8];
        h8_to_f8(H[(size_t)s0 * 16 + hl], f0);
        h8_to_f8(H[(size_t)s1 * 16 + hl], f1);
        #pragma unroll
        for (int i = 0; i < 8; ++i)
            acc[i] = fmaf(w0, f0[i], fmaf(w1, f1[i], acc[i]));
    }
    for (; j < r1; j += 2) {
        const int i0 = j + h;
        if (i0 < r1) {
            const int   s  = g_csrc[i0];
            const float ws = g_dinv[s];
            float f[8];
            h8_to_f8(H[(size_t)s * 16 + hl], f);
            #pragma unroll
            for (int i = 0; i < 8; ++i) acc[i] = fmaf(ws, f[i], acc[i]);
        }
    }

    // Combine the two halves' partial sums
    #pragma unroll
    for (int i = 0; i < 8; ++i)
        acc[i] += __shfl_xor_sync(0xffffffffu, acc[i], 16);

    // Write: half 0 writes cols [8hl, 8hl+4), half 1 writes [8hl+4, 8hl+8)
    float4* A = reinterpret_cast<float4*>(g_a);
    float4 o;
    if (h == 0) o = make_float4(acc[0], acc[1], acc[2], acc[3]);
    else        o = make_float4(acc[4], acc[5], acc[6], acc[7]);
    o.x *= dv; o.y *= dv; o.z *= dv; o.w *= dv;
    A[(size_t)v * 32 + hl * 2 + h] = o;
}

// ---------------------------------------------------------------------------
// Layer 3 fused: gather(64 cols fp16) + bias + log_softmax. Warp per node,
// SPLIT into 4 quarter-warps (one edge each); lane loads uint4 (8 halves).
// One warp LDG.128 covers 4 edges. Combine via shfl_xor(8) + shfl_xor(16).
// ---------------------------------------------------------------------------
__global__ void agg64_softmax_kernel(const float* __restrict__ b,
                                     float* __restrict__ out) {
    const int v    = blockIdx.x * (blockDim.x >> 5) + (threadIdx.x >> 5);
    const int lane = threadIdx.x & 31;
    if (v >= N_NODES) return;

    const int q  = lane >> 3;        // quarter id (0..3)
    const int ql = lane & 7;         // lane-in-quarter: cols [8*ql, 8*ql+8)
    const int   r0 = g_rowptr[v];
    const int   r1 = g_rowptr[v + 1];
    const float dv = g_dinv[v];

    const uint4* H = reinterpret_cast<const uint4*>(g_hh);   // 8 uint4 per row

    float acc[8];
    {
        float f[8];
        h8_to_f8(H[(size_t)v * 8 + ql], f);
        #pragma unroll
        for (int i = 0; i < 8; ++i) acc[i] = (q == 0) ? dv * f[i] : 0.0f;
    }

    int j = r0;
    for (; j + 3 < r1; j += 4) {     // 4 edges per iteration (1 per quarter)
        const int   s  = g_csrc[j + q];
        const float ws = g_dinv[s];
        float f[8];
        h8_to_f8(H[(size_t)s * 8 + ql], f);
        #pragma unroll
        for (int i = 0; i < 8; ++i) acc[i] = fmaf(ws, f[i], acc[i]);
    }
    if (j < r1) {
        const int i0 = j + q;
        if (i0 < r1) {
            const int   s  = g_csrc[i0];
            const float ws = g_dinv[s];
            float f[8];
            h8_to_f8(H[(size_t)s * 8 + ql], f);
            #pragma unroll
            for (int i = 0; i < 8; ++i) acc[i] = fmaf(ws, f[i], acc[i]);
        }
    }

    // Combine quarters
    #pragma unroll
    for (int i = 0; i < 8; ++i) {
        acc[i] += __shfl_xor_sync(0xffffffffu, acc[i], 8);
        acc[i] += __shfl_xor_sync(0xffffffffu, acc[i], 16);
    }

    // Bias + log_softmax over 64 cols (cols distributed over ql groups of 8)
    float val[8];
    const float4 b0 = reinterpret_cast<const float4*>(b)[2 * ql];
    const float4 b1 = reinterpret_cast<const float4*>(b)[2 * ql + 1];
    val[0] = acc[0] * dv + b0.x; val[1] = acc[1] * dv + b0.y;
    val[2] = acc[2] * dv + b0.z; val[3] = acc[3] * dv + b0.w;
    val[4] = acc[4] * dv + b1.x; val[5] = acc[5] * dv + b1.y;
    val[6] = acc[6] * dv + b1.z; val[7] = acc[7] * dv + b1.w;

    float m = val[0];
    #pragma unroll
    for (int i = 1; i < 8; ++i) m = fmaxf(m, val[i]);
    #pragma unroll
    for (int o = 4; o; o >>= 1) m = fmaxf(m, __shfl_xor_sync(0xffffffffu, m, o));
    float s = 0.0f;
    #pragma unroll
    for (int i = 0; i < 8; ++i) s += expf(val[i] - m);
    #pragma unroll
    for (int o = 4; o; o >>= 1) s += __shfl_xor_sync(0xffffffffu, s, o);
    const float lse = m + logf(s);

    // Quarters 0 and 1 write the 64 floats (16 float4 per row)
    if (q < 2) {
        float4 o4 = (q == 0)
            ? make_float4(val[0] - lse, val[1] - lse, val[2] - lse, val[3] - lse)
            : make_float4(val[4] - lse, val[5] - lse, val[6] - lse, val[7] - lse);
        reinterpret_cast<float4*>(out)[(size_t)v * 16 + ql * 2 + q] = o4;
    }
}

// ---------------------------------------------------------------------------
// Launcher (graph-capturable). Fork-join: CSR chain on a side stream overlaps
// the layer-1 GEMM on the main stream; joined before the first gather.
// ---------------------------------------------------------------------------
extern "C" void kernel_launch(void* const* d_in, const int* in_sizes, int n_in,
                              void* d_out, int out_size) {
    const float* x  = (const float*)d_in[0];
    const void*  ei = d_in[1];
    const float* W1 = (const float*)d_in[2];
    const float* b1 = (const float*)d_in[3];
    const float* W2 = (const float*)d_in[4];
    const float* b2 = (const float*)d_in[5];
    const float* W3 = (const float*)d_in[6];
    const float* b3 = (const float*)d_in[7];
    float* out = (float*)d_out;

    static cudaStream_t s_side = nullptr;
    static cudaEvent_t  s_fork = nullptr, s_join = nullptr;
    if (s_side == nullptr) {
        cudaStreamCreateWithFlags(&s_side, cudaStreamNonBlocking);
        cudaEventCreateWithFlags(&s_fork, cudaEventDisableTiming);
        cudaEventCreateWithFlags(&s_join, cudaEventDisableTiming);
    }

    const int nb_nodes = (N_NODES + 256) / 256;
    const int nb_edges = (E_EDGES + 255) / 256;

    // --- fork: CSR build on side stream ---
    cudaEventRecord(s_fork, 0);
    cudaStreamWaitEvent(s_side, s_fork, 0);

    setup_kernel<<<nb_nodes, 256, 0, s_side>>>((const int*)ei);
    hist_kernel<<<nb_edges, 256, 0, s_side>>>(ei);
    scan_block_kernel<<<SCAN_NB, SCAN_B, 0, s_side>>>();
    scan_finish_kernel<<<SCAN_NB, SCAN_B, 0, s_side>>>();
    fill_csr_kernel<<<nb_edges, 256, 0, s_side>>>(ei);
    cudaEventRecord(s_join, s_side);

    const int gemm_blocks   = (N_NODES + 127) / 128;
    const int gather_blocks = (N_NODES * 32 + 255) / 256;   // warp per node

    // --- Layer 1 GEMM overlaps the CSR build ---
    gemm_tc_kernel<HID_C, false><<<gemm_blocks, 256>>>(x, W1, nullptr);

    // --- join, then aggregate ---
    cudaStreamWaitEvent(0, s_join, 0);
    agg_gather128_kernel<<<gather_blocks, 256>>>();

    // --- Layer 2 ---
    gemm_tc_kernel<HID_C, true><<<gemm_blocks, 256>>>(nullptr, W2, b1);
    agg_gather128_kernel<<<gather_blocks, 256>>>();

    // --- Layer 3 + fused softmax ---
    gemm_tc_kernel<OUT_C, true><<<gemm_blocks, 256>>>(nullptr, W3, b2);
    agg64_softmax_kernel<<<gather_blocks, 256>>>(b3, out);
}

// round 11
// speedup vs baseline: 1.0806x; 1.0806x over previous
#include <cuda_runtime.h>
#include <cuda_fp16.h>
#include <math.h>

// Problem constants (fixed by the dataset)
#define N_NODES 100000
#define E_EDGES 1600000
#define IN_C    128
#define HID_C   128
#define OUT_C   64

#define SCAN_B   512
#define SCAN_NB  ((N_NODES + SCAN_B) / SCAN_B + 1)

typedef unsigned int uint;

// ---------------------------------------------------------------------------
// Scratch: __device__ globals
// ---------------------------------------------------------------------------
__device__ int    g_is64;
__device__ int    g_rowptr[N_NODES + 1];
__device__ int    g_cur   [N_NODES];
__device__ int    g_csrc  [E_EDGES];
__device__ int    g_bsum  [SCAN_NB];
__device__ float  g_dinv  [N_NODES];
__device__ __align__(16) __half g_hhA[(size_t)N_NODES * 128];
__device__ __align__(16) __half g_hhB[(size_t)N_NODES * 128];
__device__ __align__(16) __half g_w2t[128 * 128];   // W2^T fp16 [n][k]
__device__ __align__(16) __half g_w3t[64 * 128];    // W3^T fp16 [n][k]

// ---------------------------------------------------------------------------
// MMA helpers
// ---------------------------------------------------------------------------
__device__ __forceinline__ float to_tf32(float x) {
    float y;
    asm("cvt.rna.tf32.f32 %0, %1;" : "=f"(y) : "f"(x));
    return y;
}

__device__ __forceinline__ void mma_tf32(float c[4],
                                         uint a0, uint a1, uint a2, uint a3,
                                         uint b0, uint b1) {
    asm volatile(
        "mma.sync.aligned.m16n8k8.row.col.f32.tf32.tf32.f32 "
        "{%0,%1,%2,%3}, {%4,%5,%6,%7}, {%8,%9}, {%0,%1,%2,%3};"
        : "+f"(c[0]), "+f"(c[1]), "+f"(c[2]), "+f"(c[3])
        : "r"(a0), "r"(a1), "r"(a2), "r"(a3), "r"(b0), "r"(b1));
}

__device__ __forceinline__ void mma_f16(float c[4],
                                        uint a0, uint a1, uint a2, uint a3,
                                        uint b0, uint b1) {
    asm volatile(
        "mma.sync.aligned.m16n8k16.row.col.f32.f16.f16.f32 "
        "{%0,%1,%2,%3}, {%4,%5,%6,%7}, {%8,%9}, {%0,%1,%2,%3};"
        : "+f"(c[0]), "+f"(c[1]), "+f"(c[2]), "+f"(c[3])
        : "r"(a0), "r"(a1), "r"(a2), "r"(a3), "r"(b0), "r"(b1));
}

__device__ __forceinline__ int edge_val(const void* __restrict__ ei, long long idx) {
    if (g_is64) return (int)((const long long*)ei)[idx];
    return ((const int*)ei)[idx];
}

// Unpack 8 halves (uint4) into 8 floats
__device__ __forceinline__ void h8_to_f8(uint4 p, float f[8]) {
    float2 a = __half22float2(*reinterpret_cast<__half2*>(&p.x));
    float2 b = __half22float2(*reinterpret_cast<__half2*>(&p.y));
    float2 c = __half22float2(*reinterpret_cast<__half2*>(&p.z));
    float2 d = __half22float2(*reinterpret_cast<__half2*>(&p.w));
    f[0] = a.x; f[1] = a.y; f[2] = b.x; f[3] = b.y;
    f[4] = c.x; f[5] = c.y; f[6] = d.x; f[7] = d.y;
}

// ---------------------------------------------------------------------------
// Setup: zero rowptr + parallel dtype detect
// ---------------------------------------------------------------------------
__global__ void setup_kernel(const int* __restrict__ ei32) {
    int i = blockIdx.x * blockDim.x + threadIdx.x;
    if (i <= N_NODES) g_rowptr[i] = 0;
    if (blockIdx.x == 0 && threadIdx.x < 32) {
        int nz = (ei32[2 * threadIdx.x + 1] != 0) ? 1 : 0;
        uint any_nz = __ballot_sync(0xffffffffu, nz);
        if (threadIdx.x == 0) g_is64 = (any_nz == 0u) ? 1 : 0;
    }
}

__global__ void hist_kernel(const void* __restrict__ ei) {
    int e = blockIdx.x * blockDim.x + threadIdx.x;
    if (e < E_EDGES) {
        int d = edge_val(ei, (long long)E_EDGES + e);
        atomicAdd(&g_rowptr[d + 1], 1);
    }
}

__global__ void scan_block_kernel() {
    __shared__ int s[SCAN_B];
    const int t   = threadIdx.x;
    const int idx = blockIdx.x * SCAN_B + t;
    int v = (idx <= N_NODES) ? g_rowptr[idx] : 0;
    if (idx >= 1 && idx <= N_NODES) g_dinv[idx - 1] = rsqrtf((float)(v + 1));
    s[t] = v;
    __syncthreads();
    #pragma unroll
    for (int off = 1; off < SCAN_B; off <<= 1) {
        int add = (t >= off) ? s[t - off] : 0;
        __syncthreads();
        s[t] += add;
        __syncthreads();
    }
    if (idx <= N_NODES) g_rowptr[idx] = s[t];
    if (t == SCAN_B - 1) g_bsum[blockIdx.x] = s[t];
}

__global__ void __launch_bounds__(SCAN_B)
scan_finish_kernel() {
    __shared__ int red[SCAN_B / 32];
    const int t = threadIdx.x;
    const int b = blockIdx.x;
    int val = (t < b) ? g_bsum[t] : 0;
    #pragma unroll
    for (int o = 16; o; o >>= 1) val += __shfl_xor_sync(0xffffffffu, val, o);
    if ((t & 31) == 0) red[t >> 5] = val;
    __syncthreads();
    if (t == 0) {
        int s = 0;
        #pragma unroll
        for (int i = 0; i < SCAN_B / 32; ++i) s += red[i];
        red[0] = s;
    }
    __syncthreads();
    const int off = red[0];

    const int idx = b * SCAN_B + t;
    if (idx > N_NODES) return;
    int v = g_rowptr[idx] + off;
    g_rowptr[idx] = v;
    if (idx < N_NODES) g_cur[idx] = v;
}

__global__ void fill_csr_kernel(const void* __restrict__ ei) {
    int e = blockIdx.x * blockDim.x + threadIdx.x;
    if (e < E_EDGES) {
        int s = edge_val(ei, e);
        int d = edge_val(ei, (long long)E_EDGES + e);
        int pos = atomicAdd(&g_cur[d], 1);
        g_csrc[pos] = s;
    }
}

// Weight transpose+fp16: W [128][cols] -> dst [cols][128]
template<int COLSW>
__global__ void prep_wt_kernel(const float* __restrict__ W) {
    __half* dst = (COLSW == 128) ? g_w2t : g_w3t;
    int i = blockIdx.x * blockDim.x + threadIdx.x;
    if (i < 128 * COLSW) {
        int k = i / COLSW, n = i % COLSW;
        dst[n * 128 + k] = __float2half(W[i]);
    }
}

// ---------------------------------------------------------------------------
// Layer-1 GEMM (tf32 HMMA): g_hhA[r,:] = (half)( x[r,:] @ W1 )
// ---------------------------------------------------------------------------
__global__ void __launch_bounds__(256)
gemm1_kernel(const float* __restrict__ X, const float* __restrict__ W) {
    constexpr int K    = 128;
    constexpr int KT   = 32;
    constexpr int ROWS = 128;
    constexpr int COLS = 128;
    constexpr int WN   = 64;
    constexpr int MT   = 2;
    constexpr int NT   = 8;

    __shared__ float xs[ROWS][KT + 4];
    __shared__ float ws[KT][COLS + 4];

    const int t    = threadIdx.x;
    const int lane = t & 31;
    const int w    = t >> 5;
    const int wm   = w & 3;
    const int wn   = w >> 2;
    const int g    = lane >> 2;
    const int tig  = lane & 3;
    const int row0 = blockIdx.x * ROWS;

    float acc[MT][NT][4];
    #pragma unroll
    for (int m = 0; m < MT; ++m)
        #pragma unroll
        for (int n = 0; n < NT; ++n)
            #pragma unroll
            for (int i = 0; i < 4; ++i) acc[m][n][i] = 0.0f;

    #pragma unroll 1
    for (int kc = 0; kc < K; kc += KT) {
        for (int i = t; i < KT * COLS; i += 256) {
            const int k = i / COLS;
            const int n = i % COLS;
            ws[k][n] = to_tf32(W[(kc + k) * COLS + n]);
        }
        for (int i = t; i < ROWS * KT; i += 256) {
            const int r = i >> 5;
            const int k = i & (KT - 1);
            const int rr = row0 + r;
            xs[r][k] = (rr < N_NODES) ? to_tf32(X[(size_t)rr * K + kc + k]) : 0.0f;
        }
        __syncthreads();

        #pragma unroll
        for (int ks = 0; ks < KT / 8; ++ks) {
            const int kb = ks * 8;
            uint a[MT][4];
            #pragma unroll
            for (int m = 0; m < MT; ++m) {
                const int ar = wm * 32 + m * 16;
                a[m][0] = __float_as_uint(xs[ar + g    ][kb + tig    ]);
                a[m][1] = __float_as_uint(xs[ar + g + 8][kb + tig    ]);
                a[m][2] = __float_as_uint(xs[ar + g    ][kb + tig + 4]);
                a[m][3] = __float_as_uint(xs[ar + g + 8][kb + tig + 4]);
            }
            #pragma unroll
            for (int n = 0; n < NT; ++n) {
                const int nc = wn * WN + n * 8 + g;
                const uint b0 = __float_as_uint(ws[kb + tig    ][nc]);
                const uint b1 = __float_as_uint(ws[kb + tig + 4][nc]);
                #pragma unroll
                for (int m = 0; m < MT; ++m)
                    mma_tf32(acc[m][n], a[m][0], a[m][1], a[m][2], a[m][3], b0, b1);
            }
        }
        __syncthreads();
    }

    #pragma unroll
    for (int m = 0; m < MT; ++m) {
        const int r0 = row0 + wm * 32 + m * 16 + g;
        #pragma unroll
        for (int n = 0; n < NT; ++n) {
            const int col = wn * WN + n * 8 + 2 * tig;
            if (r0 < N_NODES)
                *reinterpret_cast<__half2*>(&g_hhA[(size_t)r0 * COLS + col]) =
                    __floats2half2_rn(acc[m][n][0], acc[m][n][1]);
            if (r0 + 8 < N_NODES)
                *reinterpret_cast<__half2*>(&g_hhA[(size_t)(r0 + 8) * COLS + col]) =
                    __floats2half2_rn(acc[m][n][2], acc[m][n][3]);
        }
    }
}

// ---------------------------------------------------------------------------
// FUSED layer: xs = relu(Ahat*Hin + b) into smem (fp16), then GEMM (fp16 HMMA)
//   Hout[r, :COLS] = xs[r, :128] @ Wt^T
// Block = 64 nodes, 256 threads. src_sel: 0 = read A write B, 1 = read B write A.
// ---------------------------------------------------------------------------
template<int COLS>
__global__ void __launch_bounds__(256)
fused_agg_gemm_kernel(int src_sel, const float* __restrict__ bprev) {
    constexpr int ROWS = 64;
    constexpr int XST  = 136;          // padded half-stride (conflict-free frags)
    constexpr int WN   = COLS / 2;
    constexpr int NT   = WN / 8;

    extern __shared__ __half smem[];
    __half* xs  = smem;                 // [64][136]
    __half* wsT = smem + ROWS * XST;    // [COLS][136]

    const __half* Hin  = src_sel ? g_hhB : g_hhA;
    __half*       Hout = src_sel ? g_hhA : g_hhB;
    const __half* Wt   = (COLS == 128) ? g_w2t : g_w3t;

    const int t    = threadIdx.x;
    const int lane = t & 31;
    const int w    = t >> 5;
    const int row0 = blockIdx.x * ROWS;

    // --- stage Wt [COLS][128] -> wsT (half2 copies) ---
    const __half2* Wt2 = reinterpret_cast<const __half2*>(Wt);
    for (int i = t; i < COLS * 64; i += 256) {
        const int n  = i >> 6;
        const int k2 = i & 63;
        *reinterpret_cast<__half2*>(&wsT[n * XST + 2 * k2]) = Wt2[i];
    }

    // --- gather phase: warp w aggregates nodes [row0+8w, row0+8w+8) ---
    {
        const int h  = lane >> 4;       // half id
        const int hl = lane & 15;       // cols [8*hl, 8*hl+8)
        float bias[8];
        #pragma unroll
        for (int i = 0; i < 8; ++i) bias[i] = bprev[8 * hl + i];
        const uint4* H4 = reinterpret_cast<const uint4*>(Hin);

        for (int r = 0; r < 8; ++r) {
            const int v = row0 + w * 8 + r;
            float acc[8];
            if (v < N_NODES) {
                const int   r0 = g_rowptr[v];
                const int   r1 = g_rowptr[v + 1];
                const float dv = g_dinv[v];
                float f[8];
                h8_to_f8(H4[(size_t)v * 16 + hl], f);
                #pragma unroll
                for (int i = 0; i < 8; ++i) acc[i] = (h == 0) ? dv * f[i] : 0.0f;

                int j = r0;
                for (; j + 3 < r1; j += 4) {
                    const int   s0 = g_csrc[j + h];
                    const int   s1 = g_csrc[j + 2 + h];
                    const float w0 = g_dinv[s0];
                    const float w1 = g_dinv[s1];
                    float f0[8], f1[8];
                    h8_to_f8(H4[(size_t)s0 * 16 + hl], f0);
                    h8_to_f8(H4[(size_t)s1 * 16 + hl], f1);
                    #pragma unroll
                    for (int i = 0; i < 8; ++i)
                        acc[i] = fmaf(w0, f0[i], fmaf(w1, f1[i], acc[i]));
                }
                for (; j < r1; j += 2) {
                    const int i0 = j + h;
                    if (i0 < r1) {
                        const int   s  = g_csrc[i0];
                        const float ws = g_dinv[s];
                        float f2[8];
                        h8_to_f8(H4[(size_t)s * 16 + hl], f2);
                        #pragma unroll
                        for (int i = 0; i < 8; ++i) acc[i] = fmaf(ws, f2[i], acc[i]);
                    }
                }
                #pragma unroll
                for (int i = 0; i < 8; ++i)
                    acc[i] += __shfl_xor_sync(0xffffffffu, acc[i], 16);
                #pragma unroll
                for (int i = 0; i < 8; ++i)
                    acc[i] = fmaxf(acc[i] * dv + bias[i], 0.0f);
            } else {
                #pragma unroll
                for (int i = 0; i < 8; ++i) acc[i] = 0.0f;
            }
            // half h writes cols [8hl+4h, 8hl+4h+4)
            const int base = (w * 8 + r) * XST + 8 * hl + 4 * h;
            *reinterpret_cast<__half2*>(&xs[base])     = __floats2half2_rn(acc[4 * h],     acc[4 * h + 1]);
            *reinterpret_cast<__half2*>(&xs[base + 2]) = __floats2half2_rn(acc[4 * h + 2], acc[4 * h + 3]);
        }
    }
    __syncthreads();

    // --- MMA phase: 8 warps as 4(M) x 2(N); warp tile 16 x WN ---
    const int wm  = w & 3;
    const int wn  = w >> 2;
    const int g   = lane >> 2;
    const int tig = lane & 3;

    float acc[NT][4];
    #pragma unroll
    for (int n = 0; n < NT; ++n)
        #pragma unroll
        for (int i = 0; i < 4; ++i) acc[n][i] = 0.0f;

    #pragma unroll
    for (int ks = 0; ks < 8; ++ks) {
        const int kb = 16 * ks;
        const int ar = (wm * 16 + g) * XST + kb + 2 * tig;
        const uint a0 = *reinterpret_cast<const uint*>(&xs[ar]);
        const uint a1 = *reinterpret_cast<const uint*>(&xs[ar + 8 * XST]);
        const uint a2 = *reinterpret_cast<const uint*>(&xs[ar + 8]);
        const uint a3 = *reinterpret_cast<const uint*>(&xs[ar + 8 * XST + 8]);
        #pragma unroll
        for (int n = 0; n < NT; ++n) {
            const int nc = wn * WN + n * 8 + g;
            const uint b0 = *reinterpret_cast<const uint*>(&wsT[nc * XST + kb + 2 * tig]);
            const uint b1 = *reinterpret_cast<const uint*>(&wsT[nc * XST + kb + 2 * tig + 8]);
            mma_f16(acc[n], a0, a1, a2, a3, b0, b1);
        }
    }

    #pragma unroll
    for (int n = 0; n < NT; ++n) {
        const int col = wn * WN + n * 8 + 2 * tig;
        const int r0g = row0 + wm * 16 + g;
        if (r0g < N_NODES)
            *reinterpret_cast<__half2*>(&Hout[(size_t)r0g * COLS + col]) =
                __floats2half2_rn(acc[n][0], acc[n][1]);
        if (r0g + 8 < N_NODES)
            *reinterpret_cast<__half2*>(&Hout[(size_t)(r0g + 8) * COLS + col]) =
                __floats2half2_rn(acc[n][2], acc[n][3]);
    }
}

// ---------------------------------------------------------------------------
// Final: gather(64 cols fp16 from g_hhA) + bias + log_softmax. Warp per node,
// split into 4 quarter-warps; lane loads uint4 (8 halves).
// ---------------------------------------------------------------------------
__global__ void agg64_softmax_kernel(const float* __restrict__ b,
                                     float* __restrict__ out) {
    const int v    = blockIdx.x * (blockDim.x >> 5) + (threadIdx.x >> 5);
    const int lane = threadIdx.x & 31;
    if (v >= N_NODES) return;

    const int q  = lane >> 3;
    const int ql = lane & 7;
    const int   r0 = g_rowptr[v];
    const int   r1 = g_rowptr[v + 1];
    const float dv = g_dinv[v];

    const uint4* H = reinterpret_cast<const uint4*>(g_hhA);   // 8 uint4 per row

    float acc[8];
    {
        float f[8];
        h8_to_f8(H[(size_t)v * 8 + ql], f);
        #pragma unroll
        for (int i = 0; i < 8; ++i) acc[i] = (q == 0) ? dv * f[i] : 0.0f;
    }

    int j = r0;
    for (; j + 3 < r1; j += 4) {
        const int   s  = g_csrc[j + q];
        const float ws = g_dinv[s];
        float f[8];
        h8_to_f8(H[(size_t)s * 8 + ql], f);
        #pragma unroll
        for (int i = 0; i < 8; ++i) acc[i] = fmaf(ws, f[i], acc[i]);
    }
    if (j < r1) {
        const int i0 = j + q;
        if (i0 < r1) {
            const int   s  = g_csrc[i0];
            const float ws = g_dinv[s];
            float f[8];
            h8_to_f8(H[(size_t)s * 8 + ql], f);
            #pragma unroll
            for (int i = 0; i < 8; ++i) acc[i] = fmaf(ws, f[i], acc[i]);
        }
    }

    #pragma unroll
    for (int i = 0; i < 8; ++i) {
        acc[i] += __shfl_xor_sync(0xffffffffu, acc[i], 8);
        acc[i] += __shfl_xor_sync(0xffffffffu, acc[i], 16);
    }

    float val[8];
    const float4 b0 = reinterpret_cast<const float4*>(b)[2 * ql];
    const float4 b1 = reinterpret_cast<const float4*>(b)[2 * ql + 1];
    val[0] = acc[0] * dv + b0.x; val[1] = acc[1] * dv + b0.y;
    val[2] = acc[2] * dv + b0.z; val[3] = acc[3] * dv + b0.w;
    val[4] = acc[4] * dv + b1.x; val[5] = acc[5] * dv + b1.y;
    val[6] = acc[6] * dv + b1.z; val[7] = acc[7] * dv + b1.w;

    float m = val[0];
    #pragma unroll
    for (int i = 1; i < 8; ++i) m = fmaxf(m, val[i]);
    #pragma unroll
    for (int o = 4; o; o >>= 1) m = fmaxf(m, __shfl_xor_sync(0xffffffffu, m, o));
    float s = 0.0f;
    #pragma unroll
    for (int i = 0; i < 8; ++i) s += expf(val[i] - m);
    #pragma unroll
    for (int o = 4; o; o >>= 1) s += __shfl_xor_sync(0xffffffffu, s, o);
    const float lse = m + logf(s);

    if (q < 2) {
        float4 o4 = (q == 0)
            ? make_float4(val[0] - lse, val[1] - lse, val[2] - lse, val[3] - lse)
            : make_float4(val[4] - lse, val[5] - lse, val[6] - lse, val[7] - lse);
        reinterpret_cast<float4*>(out)[(size_t)v * 16 + ql * 2 + q] = o4;
    }
}

// ---------------------------------------------------------------------------
// Launcher (graph-capturable). CSR + weight-prep on side stream overlap the
// layer-1 GEMM; join before the first fused layer.
// ---------------------------------------------------------------------------
extern "C" void kernel_launch(void* const* d_in, const int* in_sizes, int n_in,
                              void* d_out, int out_size) {
    const float* x  = (const float*)d_in[0];
    const void*  ei = d_in[1];
    const float* W1 = (const float*)d_in[2];
    const float* b1 = (const float*)d_in[3];
    const float* W2 = (const float*)d_in[4];
    const float* b2 = (const float*)d_in[5];
    const float* W3 = (const float*)d_in[6];
    const float* b3 = (const float*)d_in[7];
    float* out = (float*)d_out;

    static cudaStream_t s_side = nullptr;
    static cudaEvent_t  s_fork = nullptr, s_join = nullptr;
    if (s_side == nullptr) {
        cudaStreamCreateWithFlags(&s_side, cudaStreamNonBlocking);
        cudaEventCreateWithFlags(&s_fork, cudaEventDisableTiming);
        cudaEventCreateWithFlags(&s_join, cudaEventDisableTiming);
        cudaFuncSetAttribute(fused_agg_gemm_kernel<128>,
                             cudaFuncAttributeMaxDynamicSharedMemorySize, 60000);
        cudaFuncSetAttribute(fused_agg_gemm_kernel<64>,
                             cudaFuncAttributeMaxDynamicSharedMemorySize, 60000);
    }

    const int nb_nodes = (N_NODES + 256) / 256;
    const int nb_edges = (E_EDGES + 255) / 256;

    // --- fork: CSR build + weight prep on side stream ---
    cudaEventRecord(s_fork, 0);
    cudaStreamWaitEvent(s_side, s_fork, 0);

    setup_kernel<<<nb_nodes, 256, 0, s_side>>>((const int*)ei);
    hist_kernel<<<nb_edges, 256, 0, s_side>>>(ei);
    scan_block_kernel<<<SCAN_NB, SCAN_B, 0, s_side>>>();
    scan_finish_kernel<<<SCAN_NB, SCAN_B, 0, s_side>>>();
    fill_csr_kernel<<<nb_edges, 256, 0, s_side>>>(ei);
    prep_wt_kernel<128><<<(128 * 128 + 255) / 256, 256, 0, s_side>>>(W2);
    prep_wt_kernel<64><<<(128 * 64 + 255) / 256, 256, 0, s_side>>>(W3);
    cudaEventRecord(s_join, s_side);

    // --- Layer 1 GEMM overlaps the CSR build ---
    gemm1_kernel<<<(N_NODES + 127) / 128, 256>>>(x, W1);

    // --- join ---
    cudaStreamWaitEvent(0, s_join, 0);

    // --- Fused layers 2 & 3 ---
    const int fused_blocks = (N_NODES + 63) / 64;
    constexpr int SMEM2 = (64 + 128) * 136 * 2;   // 52224 B
    constexpr int SMEM3 = (64 + 64) * 136 * 2;    // 34816 B
    fused_agg_gemm_kernel<128><<<fused_blocks, 256, SMEM2>>>(0, b1);  // A -> B
    fused_agg_gemm_kernel<64> <<<fused_blocks, 256, SMEM3>>>(1, b2);  // B -> A

    // --- Final: gather + bias + log_softmax ---
    const int gather_blocks = (N_NODES * 32 + 255) / 256;
    agg64_softmax_kernel<<<gather_blocks, 256>>>(b3, out);
}

// round 12
// speedup vs baseline: 1.0821x; 1.0014x over previous
#include <cuda_runtime.h>
#include <cuda_fp16.h>
#include <math.h>

// Problem constants (fixed by the dataset)
#define N_NODES 100000
#define E_EDGES 1600000
#define IN_C    128
#define HID_C   128
#define OUT_C   64

#define SCAN_B   512
#define SCAN_NB  ((N_NODES + SCAN_B) / SCAN_B + 1)

typedef unsigned int uint;

// ---------------------------------------------------------------------------
// Scratch: __device__ globals
// ---------------------------------------------------------------------------
__device__ int    g_is64;
__device__ int    g_rowptr[N_NODES + 1];
__device__ int    g_cur   [N_NODES];
__device__ int2   g_edge  [E_EDGES];    // {src, __float_as_int(dinv[src])}
__device__ int    g_bsum  [SCAN_NB];
__device__ float  g_dinv  [N_NODES];
__device__ __align__(16) __half g_hhA[(size_t)N_NODES * 128];
__device__ __align__(16) __half g_hhB[(size_t)N_NODES * 128];
__device__ __align__(16) __half g_w2t[128 * 128];   // W2^T fp16 [n][k]
__device__ __align__(16) __half g_w3t[64 * 128];    // W3^T fp16 [n][k]

// ---------------------------------------------------------------------------
// MMA helpers
// ---------------------------------------------------------------------------
__device__ __forceinline__ float to_tf32(float x) {
    float y;
    asm("cvt.rna.tf32.f32 %0, %1;" : "=f"(y) : "f"(x));
    return y;
}

__device__ __forceinline__ void mma_tf32(float c[4],
                                         uint a0, uint a1, uint a2, uint a3,
                                         uint b0, uint b1) {
    asm volatile(
        "mma.sync.aligned.m16n8k8.row.col.f32.tf32.tf32.f32 "
        "{%0,%1,%2,%3}, {%4,%5,%6,%7}, {%8,%9}, {%0,%1,%2,%3};"
        : "+f"(c[0]), "+f"(c[1]), "+f"(c[2]), "+f"(c[3])
        : "r"(a0), "r"(a1), "r"(a2), "r"(a3), "r"(b0), "r"(b1));
}

__device__ __forceinline__ void mma_f16(float c[4],
                                        uint a0, uint a1, uint a2, uint a3,
                                        uint b0, uint b1) {
    asm volatile(
        "mma.sync.aligned.m16n8k16.row.col.f32.f16.f16.f32 "
        "{%0,%1,%2,%3}, {%4,%5,%6,%7}, {%8,%9}, {%0,%1,%2,%3};"
        : "+f"(c[0]), "+f"(c[1]), "+f"(c[2]), "+f"(c[3])
        : "r"(a0), "r"(a1), "r"(a2), "r"(a3), "r"(b0), "r"(b1));
}

__device__ __forceinline__ int edge_val(const void* __restrict__ ei, long long idx) {
    if (g_is64) return (int)((const long long*)ei)[idx];
    return ((const int*)ei)[idx];
}

// Unpack 8 halves (uint4) into 8 floats
__device__ __forceinline__ void h8_to_f8(uint4 p, float f[8]) {
    float2 a = __half22float2(*reinterpret_cast<__half2*>(&p.x));
    float2 b = __half22float2(*reinterpret_cast<__half2*>(&p.y));
    float2 c = __half22float2(*reinterpret_cast<__half2*>(&p.z));
    float2 d = __half22float2(*reinterpret_cast<__half2*>(&p.w));
    f[0] = a.x; f[1] = a.y; f[2] = b.x; f[3] = b.y;
    f[4] = c.x; f[5] = c.y; f[6] = d.x; f[7] = d.y;
}

// ---------------------------------------------------------------------------
// Setup: zero rowptr + parallel dtype detect
// ---------------------------------------------------------------------------
__global__ void setup_kernel(const int* __restrict__ ei32) {
    int i = blockIdx.x * blockDim.x + threadIdx.x;
    if (i <= N_NODES) g_rowptr[i] = 0;
    if (blockIdx.x == 0 && threadIdx.x < 32) {
        int nz = (ei32[2 * threadIdx.x + 1] != 0) ? 1 : 0;
        uint any_nz = __ballot_sync(0xffffffffu, nz);
        if (threadIdx.x == 0) g_is64 = (any_nz == 0u) ? 1 : 0;
    }
}

__global__ void hist_kernel(const void* __restrict__ ei) {
    int e = blockIdx.x * blockDim.x + threadIdx.x;
    if (e < E_EDGES) {
        int d = edge_val(ei, (long long)E_EDGES + e);
        atomicAdd(&g_rowptr[d + 1], 1);
    }
}

__global__ void scan_block_kernel() {
    __shared__ int s[SCAN_B];
    const int t   = threadIdx.x;
    const int idx = blockIdx.x * SCAN_B + t;
    int v = (idx <= N_NODES) ? g_rowptr[idx] : 0;
    if (idx >= 1 && idx <= N_NODES) g_dinv[idx - 1] = rsqrtf((float)(v + 1));
    s[t] = v;
    __syncthreads();
    #pragma unroll
    for (int off = 1; off < SCAN_B; off <<= 1) {
        int add = (t >= off) ? s[t - off] : 0;
        __syncthreads();
        s[t] += add;
        __syncthreads();
    }
    if (idx <= N_NODES) g_rowptr[idx] = s[t];
    if (t == SCAN_B - 1) g_bsum[blockIdx.x] = s[t];
}

__global__ void __launch_bounds__(SCAN_B)
scan_finish_kernel() {
    __shared__ int red[SCAN_B / 32];
    const int t = threadIdx.x;
    const int b = blockIdx.x;
    int val = (t < b) ? g_bsum[t] : 0;
    #pragma unroll
    for (int o = 16; o; o >>= 1) val += __shfl_xor_sync(0xffffffffu, val, o);
    if ((t & 31) == 0) red[t >> 5] = val;
    __syncthreads();
    if (t == 0) {
        int s = 0;
        #pragma unroll
        for (int i = 0; i < SCAN_B / 32; ++i) s += red[i];
        red[0] = s;
    }
    __syncthreads();
    const int off = red[0];

    const int idx = b * SCAN_B + t;
    if (idx > N_NODES) return;
    int v = g_rowptr[idx] + off;
    g_rowptr[idx] = v;
    if (idx < N_NODES) g_cur[idx] = v;
}

// Fill edge records {src, dinv[src]} (dinv ready after scan_block)
__global__ void fill_csr_kernel(const void* __restrict__ ei) {
    int e = blockIdx.x * blockDim.x + threadIdx.x;
    if (e < E_EDGES) {
        int s = edge_val(ei, e);
        int d = edge_val(ei, (long long)E_EDGES + e);
        int pos = atomicAdd(&g_cur[d], 1);
        g_edge[pos] = make_int2(s, __float_as_int(g_dinv[s]));
    }
}

// Weight transpose+fp16: W [128][cols] -> dst [cols][128]
template<int COLSW>
__global__ void prep_wt_kernel(const float* __restrict__ W) {
    __half* dst = (COLSW == 128) ? g_w2t : g_w3t;
    int i = blockIdx.x * blockDim.x + threadIdx.x;
    if (i < 128 * COLSW) {
        int k = i / COLSW, n = i % COLSW;
        dst[n * 128 + k] = __float2half(W[i]);
    }
}

// ---------------------------------------------------------------------------
// Layer-1 GEMM (tf32 HMMA): g_hhA[r,:] = (half)( x[r,:] @ W1 )  (unscaled)
// ---------------------------------------------------------------------------
__global__ void __launch_bounds__(256)
gemm1_kernel(const float* __restrict__ X, const float* __restrict__ W) {
    constexpr int K    = 128;
    constexpr int KT   = 32;
    constexpr int ROWS = 128;
    constexpr int COLS = 128;
    constexpr int WN   = 64;
    constexpr int MT   = 2;
    constexpr int NT   = 8;

    __shared__ float xs[ROWS][KT + 4];
    __shared__ float ws[KT][COLS + 4];

    const int t    = threadIdx.x;
    const int lane = t & 31;
    const int w    = t >> 5;
    const int wm   = w & 3;
    const int wn   = w >> 2;
    const int g    = lane >> 2;
    const int tig  = lane & 3;
    const int row0 = blockIdx.x * ROWS;

    float acc[MT][NT][4];
    #pragma unroll
    for (int m = 0; m < MT; ++m)
        #pragma unroll
        for (int n = 0; n < NT; ++n)
            #pragma unroll
            for (int i = 0; i < 4; ++i) acc[m][n][i] = 0.0f;

    #pragma unroll 1
    for (int kc = 0; kc < K; kc += KT) {
        for (int i = t; i < KT * COLS; i += 256) {
            const int k = i / COLS;
            const int n = i % COLS;
            ws[k][n] = to_tf32(W[(kc + k) * COLS + n]);
        }
        for (int i = t; i < ROWS * KT; i += 256) {
            const int r = i >> 5;
            const int k = i & (KT - 1);
            const int rr = row0 + r;
            xs[r][k] = (rr < N_NODES) ? to_tf32(X[(size_t)rr * K + kc + k]) : 0.0f;
        }
        __syncthreads();

        #pragma unroll
        for (int ks = 0; ks < KT / 8; ++ks) {
            const int kb = ks * 8;
            uint a[MT][4];
            #pragma unroll
            for (int m = 0; m < MT; ++m) {
                const int ar = wm * 32 + m * 16;
                a[m][0] = __float_as_uint(xs[ar + g    ][kb + tig    ]);
                a[m][1] = __float_as_uint(xs[ar + g + 8][kb + tig    ]);
                a[m][2] = __float_as_uint(xs[ar + g    ][kb + tig + 4]);
                a[m][3] = __float_as_uint(xs[ar + g + 8][kb + tig + 4]);
            }
            #pragma unroll
            for (int n = 0; n < NT; ++n) {
                const int nc = wn * WN + n * 8 + g;
                const uint b0 = __float_as_uint(ws[kb + tig    ][nc]);
                const uint b1 = __float_as_uint(ws[kb + tig + 4][nc]);
                #pragma unroll
                for (int m = 0; m < MT; ++m)
                    mma_tf32(acc[m][n], a[m][0], a[m][1], a[m][2], a[m][3], b0, b1);
            }
        }
        __syncthreads();
    }

    #pragma unroll
    for (int m = 0; m < MT; ++m) {
        const int r0 = row0 + wm * 32 + m * 16 + g;
        #pragma unroll
        for (int n = 0; n < NT; ++n) {
            const int col = wn * WN + n * 8 + 2 * tig;
            if (r0 < N_NODES)
                *reinterpret_cast<__half2*>(&g_hhA[(size_t)r0 * COLS + col]) =
                    __floats2half2_rn(acc[m][n][0], acc[m][n][1]);
            if (r0 + 8 < N_NODES)
                *reinterpret_cast<__half2*>(&g_hhA[(size_t)(r0 + 8) * COLS + col]) =
                    __floats2half2_rn(acc[m][n][2], acc[m][n][3]);
        }
    }
}

// ---------------------------------------------------------------------------
// FUSED layer: xs = relu(Ahat*Hin + b) into smem (fp16), then fp16 HMMA GEMM.
// WEIGHTED: Hin unscaled, per-edge weight from g_edge.y (layer 2).
// !WEIGHTED: Hin rows pre-scaled by dinv[src]; plain row sum (layer 3).
// Epilogue writes Hout PRE-SCALED by dinv[row].
// ---------------------------------------------------------------------------
template<int COLS, bool WEIGHTED>
__global__ void __launch_bounds__(256)
fused_agg_gemm_kernel(int src_sel, const float* __restrict__ bprev) {
    constexpr int ROWS = 64;
    constexpr int XST  = 136;
    constexpr int WN   = COLS / 2;
    constexpr int NT   = WN / 8;

    extern __shared__ __half smem[];
    __half* xs  = smem;                 // [64][136]
    __half* wsT = smem + ROWS * XST;    // [COLS][136]

    const __half* Hin  = src_sel ? g_hhB : g_hhA;
    __half*       Hout = src_sel ? g_hhA : g_hhB;
    const __half* Wt   = (COLS == 128) ? g_w2t : g_w3t;

    const int t    = threadIdx.x;
    const int lane = t & 31;
    const int w    = t >> 5;
    const int row0 = blockIdx.x * ROWS;

    // --- stage Wt [COLS][128] -> wsT ---
    const __half2* Wt2 = reinterpret_cast<const __half2*>(Wt);
    for (int i = t; i < COLS * 64; i += 256) {
        const int n  = i >> 6;
        const int k2 = i & 63;
        *reinterpret_cast<__half2*>(&wsT[n * XST + 2 * k2]) = Wt2[i];
    }

    // --- gather phase: warp w aggregates nodes [row0+8w, row0+8w+8) ---
    {
        const int h  = lane >> 4;
        const int hl = lane & 15;
        float bias[8];
        #pragma unroll
        for (int i = 0; i < 8; ++i) bias[i] = bprev[8 * hl + i];
        const uint4* H4 = reinterpret_cast<const uint4*>(Hin);

        for (int r = 0; r < 8; ++r) {
            const int v = row0 + w * 8 + r;
            float acc[8];
            if (v < N_NODES) {
                const int   r0 = g_rowptr[v];
                const int   r1 = g_rowptr[v + 1];
                const float dv = g_dinv[v];
                float f[8];
                h8_to_f8(H4[(size_t)v * 16 + hl], f);
                #pragma unroll
                for (int i = 0; i < 8; ++i) acc[i] = (h == 0) ? dv * f[i] : 0.0f;

                int j = r0;
                // 8 edges per warp-iter (4 per half): 4-deep MLP on both levels
                for (; j + 7 < r1; j += 8) {
                    const int2 e0 = g_edge[j + h];
                    const int2 e1 = g_edge[j + 2 + h];
                    const int2 e2 = g_edge[j + 4 + h];
                    const int2 e3 = g_edge[j + 6 + h];
                    float f0[8], f1[8], f2[8], f3[8];
                    h8_to_f8(H4[(size_t)e0.x * 16 + hl], f0);
                    h8_to_f8(H4[(size_t)e1.x * 16 + hl], f1);
                    h8_to_f8(H4[(size_t)e2.x * 16 + hl], f2);
                    h8_to_f8(H4[(size_t)e3.x * 16 + hl], f3);
                    if (WEIGHTED) {
                        const float w0 = __int_as_float(e0.y);
                        const float w1 = __int_as_float(e1.y);
                        const float w2 = __int_as_float(e2.y);
                        const float w3 = __int_as_float(e3.y);
                        #pragma unroll
                        for (int i = 0; i < 8; ++i)
                            acc[i] = fmaf(w0, f0[i], fmaf(w1, f1[i],
                                     fmaf(w2, f2[i], fmaf(w3, f3[i], acc[i]))));
                    } else {
                        #pragma unroll
                        for (int i = 0; i < 8; ++i)
                            acc[i] += (f0[i] + f1[i]) + (f2[i] + f3[i]);
                    }
                }
                for (; j < r1; j += 2) {
                    const int i0 = j + h;
                    if (i0 < r1) {
                        const int2 e = g_edge[i0];
                        float fe[8];
                        h8_to_f8(H4[(size_t)e.x * 16 + hl], fe);
                        if (WEIGHTED) {
                            const float we = __int_as_float(e.y);
                            #pragma unroll
                            for (int i = 0; i < 8; ++i) acc[i] = fmaf(we, fe[i], acc[i]);
                        } else {
                            #pragma unroll
                            for (int i = 0; i < 8; ++i) acc[i] += fe[i];
                        }
                    }
                }
                #pragma unroll
                for (int i = 0; i < 8; ++i)
                    acc[i] += __shfl_xor_sync(0xffffffffu, acc[i], 16);
                #pragma unroll
                for (int i = 0; i < 8; ++i)
                    acc[i] = fmaxf(acc[i] * dv + bias[i], 0.0f);
            } else {
                #pragma unroll
                for (int i = 0; i < 8; ++i) acc[i] = 0.0f;
            }
            const int base = (w * 8 + r) * XST + 8 * hl + 4 * h;
            *reinterpret_cast<__half2*>(&xs[base])     = __floats2half2_rn(acc[4 * h],     acc[4 * h + 1]);
            *reinterpret_cast<__half2*>(&xs[base + 2]) = __floats2half2_rn(acc[4 * h + 2], acc[4 * h + 3]);
        }
    }
    __syncthreads();

    // --- MMA phase: 8 warps as 4(M) x 2(N); warp tile 16 x WN ---
    const int wm  = w & 3;
    const int wn  = w >> 2;
    const int g   = lane >> 2;
    const int tig = lane & 3;

    float acc[NT][4];
    #pragma unroll
    for (int n = 0; n < NT; ++n)
        #pragma unroll
        for (int i = 0; i < 4; ++i) acc[n][i] = 0.0f;

    #pragma unroll
    for (int ks = 0; ks < 8; ++ks) {
        const int kb = 16 * ks;
        const int ar = (wm * 16 + g) * XST + kb + 2 * tig;
        const uint a0 = *reinterpret_cast<const uint*>(&xs[ar]);
        const uint a1 = *reinterpret_cast<const uint*>(&xs[ar + 8 * XST]);
        const uint a2 = *reinterpret_cast<const uint*>(&xs[ar + 8]);
        const uint a3 = *reinterpret_cast<const uint*>(&xs[ar + 8 * XST + 8]);
        #pragma unroll
        for (int n = 0; n < NT; ++n) {
            const int nc = wn * WN + n * 8 + g;
            const uint b0 = *reinterpret_cast<const uint*>(&wsT[nc * XST + kb + 2 * tig]);
            const uint b1 = *reinterpret_cast<const uint*>(&wsT[nc * XST + kb + 2 * tig + 8]);
            mma_f16(acc[n], a0, a1, a2, a3, b0, b1);
        }
    }

    // Epilogue: PRE-SCALE rows by dinv[row] so downstream gathers skip weights
    const int r0g = row0 + wm * 16 + g;
    const float dv0 = (r0g     < N_NODES) ? g_dinv[r0g]     : 0.0f;
    const float dv1 = (r0g + 8 < N_NODES) ? g_dinv[r0g + 8] : 0.0f;
    #pragma unroll
    for (int n = 0; n < NT; ++n) {
        const int col = wn * WN + n * 8 + 2 * tig;
        if (r0g < N_NODES)
            *reinterpret_cast<__half2*>(&Hout[(size_t)r0g * COLS + col]) =
                __floats2half2_rn(dv0 * acc[n][0], dv0 * acc[n][1]);
        if (r0g + 8 < N_NODES)
            *reinterpret_cast<__half2*>(&Hout[(size_t)(r0g + 8) * COLS + col]) =
                __floats2half2_rn(dv1 * acc[n][2], dv1 * acc[n][3]);
    }
}

// ---------------------------------------------------------------------------
// Final: gather(64 cols, PRE-SCALED rows from g_hhA) + bias + log_softmax.
// Warp per node, 4 quarter-warps; plain row sums, 8 edges per warp-iter.
// ---------------------------------------------------------------------------
__global__ void agg64_softmax_kernel(const float* __restrict__ b,
                                     float* __restrict__ out) {
    const int v    = blockIdx.x * (blockDim.x >> 5) + (threadIdx.x >> 5);
    const int lane = threadIdx.x & 31;
    if (v >= N_NODES) return;

    const int q  = lane >> 3;
    const int ql = lane & 7;
    const int   r0 = g_rowptr[v];
    const int   r1 = g_rowptr[v + 1];
    const float dv = g_dinv[v];

    const uint4* H = reinterpret_cast<const uint4*>(g_hhA);   // 8 uint4 per row

    float acc[8];
    {
        float f[8];
        h8_to_f8(H[(size_t)v * 8 + ql], f);
        #pragma unroll
        for (int i = 0; i < 8; ++i) acc[i] = (q == 0) ? f[i] : 0.0f;  // pre-scaled
    }

    int j = r0;
    for (; j + 7 < r1; j += 8) {       // 8 edges per warp-iter (2 per quarter)
        const int s0 = g_edge[j + q].x;
        const int s1 = g_edge[j + 4 + q].x;
        float f0[8], f1[8];
        h8_to_f8(H[(size_t)s0 * 8 + ql], f0);
        h8_to_f8(H[(size_t)s1 * 8 + ql], f1);
        #pragma unroll
        for (int i = 0; i < 8; ++i) acc[i] += f0[i] + f1[i];
    }
    for (; j < r1; j += 4) {
        const int i0 = j + q;
        if (i0 < r1) {
            const int s = g_edge[i0].x;
            float f[8];
            h8_to_f8(H[(size_t)s * 8 + ql], f);
            #pragma unroll
            for (int i = 0; i < 8; ++i) acc[i] += f[i];
        }
    }

    #pragma unroll
    for (int i = 0; i < 8; ++i) {
        acc[i] += __shfl_xor_sync(0xffffffffu, acc[i], 8);
        acc[i] += __shfl_xor_sync(0xffffffffu, acc[i], 16);
    }

    float val[8];
    const float4 b0 = reinterpret_cast<const float4*>(b)[2 * ql];
    const float4 b1 = reinterpret_cast<const float4*>(b)[2 * ql + 1];
    val[0] = acc[0] * dv + b0.x; val[1] = acc[1] * dv + b0.y;
    val[2] = acc[2] * dv + b0.z; val[3] = acc[3] * dv + b0.w;
    val[4] = acc[4] * dv + b1.x; val[5] = acc[5] * dv + b1.y;
    val[6] = acc[6] * dv + b1.z; val[7] = acc[7] * dv + b1.w;

    float m = val[0];
    #pragma unroll
    for (int i = 1; i < 8; ++i) m = fmaxf(m, val[i]);
    #pragma unroll
    for (int o = 4; o; o >>= 1) m = fmaxf(m, __shfl_xor_sync(0xffffffffu, m, o));
    float s = 0.0f;
    #pragma unroll
    for (int i = 0; i < 8; ++i) s += expf(val[i] - m);
    #pragma unroll
    for (int o = 4; o; o >>= 1) s += __shfl_xor_sync(0xffffffffu, s, o);
    const float lse = m + logf(s);

    if (q < 2) {
        float4 o4 = (q == 0)
            ? make_float4(val[0] - lse, val[1] - lse, val[2] - lse, val[3] - lse)
            : make_float4(val[4] - lse, val[5] - lse, val[6] - lse, val[7] - lse);
        reinterpret_cast<float4*>(out)[(size_t)v * 16 + ql * 2 + q] = o4;
    }
}

// ---------------------------------------------------------------------------
// Launcher (graph-capturable). CSR + weight prep on side stream overlap the
// layer-1 GEMM; join before the first fused layer.
// ---------------------------------------------------------------------------
extern "C" void kernel_launch(void* const* d_in, const int* in_sizes, int n_in,
                              void* d_out, int out_size) {
    const float* x  = (const float*)d_in[0];
    const void*  ei = d_in[1];
    const float* W1 = (const float*)d_in[2];
    const float* b1 = (const float*)d_in[3];
    const float* W2 = (const float*)d_in[4];
    const float* b2 = (const float*)d_in[5];
    const float* W3 = (const float*)d_in[6];
    const float* b3 = (const float*)d_in[7];
    float* out = (float*)d_out;

    static cudaStream_t s_side = nullptr;
    static cudaEvent_t  s_fork = nullptr, s_join = nullptr;
    if (s_side == nullptr) {
        cudaStreamCreateWithFlags(&s_side, cudaStreamNonBlocking);
        cudaEventCreateWithFlags(&s_fork, cudaEventDisableTiming);
        cudaEventCreateWithFlags(&s_join, cudaEventDisableTiming);
        cudaFuncSetAttribute((const void*)fused_agg_gemm_kernel<128, true>,
                             cudaFuncAttributeMaxDynamicSharedMemorySize, 60000);
        cudaFuncSetAttribute((const void*)fused_agg_gemm_kernel<64, false>,
                             cudaFuncAttributeMaxDynamicSharedMemorySize, 60000);
    }

    const int nb_nodes = (N_NODES + 256) / 256;
    const int nb_edges = (E_EDGES + 255) / 256;

    // --- fork: CSR build + weight prep on side stream ---
    cudaEventRecord(s_fork, 0);
    cudaStreamWaitEvent(s_side, s_fork, 0);

    setup_kernel<<<nb_nodes, 256, 0, s_side>>>((const int*)ei);
    hist_kernel<<<nb_edges, 256, 0, s_side>>>(ei);
    scan_block_kernel<<<SCAN_NB, SCAN_B, 0, s_side>>>();
    scan_finish_kernel<<<SCAN_NB, SCAN_B, 0, s_side>>>();
    fill_csr_kernel<<<nb_edges, 256, 0, s_side>>>(ei);
    prep_wt_kernel<128><<<(128 * 128 + 255) / 256, 256, 0, s_side>>>(W2);
    prep_wt_kernel<64><<<(128 * 64 + 255) / 256, 256, 0, s_side>>>(W3);
    cudaEventRecord(s_join, s_side);

    // --- Layer 1 GEMM overlaps the CSR build ---
    gemm1_kernel<<<(N_NODES + 127) / 128, 256>>>(x, W1);

    // --- join ---
    cudaStreamWaitEvent(0, s_join, 0);

    // --- Fused layers 2 & 3 ---
    const int fused_blocks = (N_NODES + 63) / 64;
    constexpr int SMEM2 = (64 + 128) * 136 * 2;   // 52224 B
    constexpr int SMEM3 = (64 + 64) * 136 * 2;    // 34816 B
    fused_agg_gemm_kernel<128, true ><<<fused_blocks, 256, SMEM2>>>(0, b1);  // A -> B
    fused_agg_gemm_kernel<64,  false><<<fused_blocks, 256, SMEM3>>>(1, b2);  // B -> A

    // --- Final: gather + bias + log_softmax ---
    const int gather_blocks = (N_NODES * 32 + 255) / 256;
    agg64_softmax_kernel<<<gather_blocks, 256>>>(b3, out);
}